// round 12
// baseline (speedup 1.0000x reference)
#include <cuda_runtime.h>
#include <cuda_bf16.h>

// InterLayerTrajectoryFlow: fused streaming diff -> L2-normalize -> causal
// 6-tap weighted sum. fp32 in/out, [B=8, S=8192, D=512].
//
// R6 profile: chain-bound (issue 47.5%, dram 52.4%, nothing saturated) on the
// per-row reduce+barrier dependency chain. R7: DOUBLE-STEP — two diffs, two
// outputs per barrier. One interleaved dual shfl tree (same serial depth as
// one), ONE __syncthreads per two rows, triple-buffered smem parity (period-3
// reuse, safe). Ring period-6 with 2 writes/step -> unroll 3, zero-MOV
// rotations. 6-deep load pipeline, 2 refills/step (3-step DRAM lookahead).

namespace {
constexpr int D      = 512;
constexpr int DV     = D / 4;     // float4 per row = 128
constexpr int CHUNK  = 64;        // positions per block
constexpr int NTHR   = DV;        // 128 threads
constexpr int BATCH  = 8;
}

// Double step: consumes pipeline rows PA(=row r), PB(=r+1), PC(=r+2);
// computes diffs dA=r->r+1, dB=r+1->r+2; refills PA<-row refillA(=r+6),
// PB<-refillB(=r+7). Ring: writes RA<-dA, RB<-dB; e1..e4 are diffs of ages
// 1..4; age-5 diff is the OLD value of RB (read before overwrite).
// Outputs pos outpos (w1) and outpos+1 (w2).
__device__ __forceinline__ void dstep(
    const float4* __restrict__ base, float4* __restrict__ obase,
    int refillA, int refillB, int outpos, int lane,
    float4& PA, float4& PB, const float4& PC,
    float4& RA, float4& RB,
    const float4& e1, const float4& e2, const float4& e3, const float4& e4,
    const float (&cf)[6], float* red, int par, int wid, int lid,
    bool w1, bool w2)
{
    float4 dA, dB;
    dA.x = PB.x - PA.x; dA.y = PB.y - PA.y; dA.z = PB.z - PA.z; dA.w = PB.w - PA.w;
    dB.x = PC.x - PB.x; dB.y = PC.y - PB.y; dB.z = PC.z - PB.z; dB.w = PC.w - PB.w;
    PA = __ldg(&base[(size_t)refillA * DV + lane]);
    PB = __ldg(&base[(size_t)refillB * DV + lane]);
    float sa = dA.x*dA.x + dA.y*dA.y + dA.z*dA.z + dA.w*dA.w;
    float sb = dB.x*dB.x + dB.y*dB.y + dB.z*dB.z + dB.w*dB.w;
#pragma unroll
    for (int o = 16; o > 0; o >>= 1) {
        sa += __shfl_xor_sync(0xffffffffu, sa, o);
        sb += __shfl_xor_sync(0xffffffffu, sb, o);
    }
    if (lid == 0) { red[par * 8 + wid] = sa; red[par * 8 + 4 + wid] = sb; }
    __syncthreads();
    sa = (red[par*8 + 0] + red[par*8 + 1]) + (red[par*8 + 2] + red[par*8 + 3]);
    sb = (red[par*8 + 4] + red[par*8 + 5]) + (red[par*8 + 6] + red[par*8 + 7]);
    // 1/(sqrt(s)+1e-8) ~= t - 1e-8*t^2 (t = rsqrt(s)); gate mag > 1e-6.
    float ta = rsqrtf(sa), tb = rsqrtf(sb);
    float ia = (sa > 1e-12f) ? fmaf(-1e-8f * ta, ta, ta) : 0.0f;
    float ib = (sb > 1e-12f) ? fmaf(-1e-8f * tb, tb, tb) : 0.0f;
    dA.x *= ia; dA.y *= ia; dA.z *= ia; dA.w *= ia;
    dB.x *= ib; dB.y *= ib; dB.z *= ib; dB.w *= ib;
    if (w1) {  // pos = t+1 : ages 0..5 = dA, e1..e4, oldRB
        float4 a;
        a.x = cf[0]*dA.x + cf[1]*e1.x + cf[2]*e2.x + cf[3]*e3.x + cf[4]*e4.x + cf[5]*RB.x;
        a.y = cf[0]*dA.y + cf[1]*e1.y + cf[2]*e2.y + cf[3]*e3.y + cf[4]*e4.y + cf[5]*RB.y;
        a.z = cf[0]*dA.z + cf[1]*e1.z + cf[2]*e2.z + cf[3]*e3.z + cf[4]*e4.z + cf[5]*RB.z;
        a.w = cf[0]*dA.w + cf[1]*e1.w + cf[2]*e2.w + cf[3]*e3.w + cf[4]*e4.w + cf[5]*RB.w;
        obase[(size_t)outpos * DV + lane] = a;
    }
    if (w2) {  // pos = t+2 : ages 0..5 = dB, dA, e1..e4
        float4 a;
        a.x = cf[0]*dB.x + cf[1]*dA.x + cf[2]*e1.x + cf[3]*e2.x + cf[4]*e3.x + cf[5]*e4.x;
        a.y = cf[0]*dB.y + cf[1]*dA.y + cf[2]*e1.y + cf[3]*e2.y + cf[4]*e3.y + cf[5]*e4.y;
        a.z = cf[0]*dB.z + cf[1]*dA.z + cf[2]*e1.z + cf[3]*e2.z + cf[4]*e3.z + cf[5]*e4.z;
        a.w = cf[0]*dB.w + cf[1]*dA.w + cf[2]*e1.w + cf[3]*e2.w + cf[4]*e3.w + cf[5]*e4.w;
        obase[(size_t)(outpos + 1) * DV + lane] = a;
    }
    RA = dA; RB = dB;
}

__device__ __forceinline__ float warp_reduce_add(float v) {
#pragma unroll
    for (int o = 16; o > 0; o >>= 1)
        v += __shfl_xor_sync(0xffffffffu, v, o);
    return v;
}

__global__ void __launch_bounds__(NTHR, 7)
traj_flow_kernel(const float* __restrict__ emb,
                 const int* __restrict__ layer_idx_p,
                 float* __restrict__ out, int S) {
    __shared__ float red[24];  // 3 parities x 8 slots

    const int b    = blockIdx.y;
    const int p0   = blockIdx.x * CHUNK;
    const int lane = threadIdx.x;
    const int wid  = lane >> 5;
    const int lid  = lane & 31;

    const float4* base  = reinterpret_cast<const float4*>(emb) + (size_t)b * S * DV;
    float4*       obase = reinterpret_cast<float4*>(out)       + (size_t)b * S * DV;

    const float scale = 0.1f * (1.0f + (float)(*layer_idx_p) * 0.8f);

    float cf[6];
    {
        float wsum = 0.0f;
#pragma unroll
        for (int k = 0; k < 6; ++k) { cf[k] = expf(-(float)k * 0.2f); wsum += cf[k]; }
        const float c = scale / (wsum + 1e-8f);
#pragma unroll
        for (int k = 0; k < 6; ++k) cf[k] *= c;
    }

    float4 z4; z4.x = z4.y = z4.z = z4.w = 0.0f;
    const int nout = min(CHUNK, S - p0);

    if (p0 == 0) {
        // ---- slow path (8 blocks): generic single-step with pos<6 specials ----
        float4 n0 = z4, n1 = z4, n2 = z4, n3 = z4, n4 = z4, n5 = z4;
        float4 cur = __ldg(&base[lane]);
        float4 nxt = __ldg(&base[(size_t)1 * DV + lane]);
        for (int tt = 0; tt <= nout - 2; ++tt) {
            float4 d;
            d.x = nxt.x - cur.x; d.y = nxt.y - cur.y;
            d.z = nxt.z - cur.z; d.w = nxt.w - cur.w;
            cur = nxt;
            nxt = __ldg(&base[(size_t)min(tt + 2, S - 1) * DV + lane]);
            float ss = d.x*d.x + d.y*d.y + d.z*d.z + d.w*d.w;
            ss = warp_reduce_add(ss);
            const int par = tt & 1;
            if (lid == 0) red[par * 4 + wid] = ss;
            __syncthreads();
            ss = (red[par*4 + 0] + red[par*4 + 1]) + (red[par*4 + 2] + red[par*4 + 3]);
            float t   = rsqrtf(ss);
            float inv = (ss > 1e-12f) ? fmaf(-1e-8f * t, t, t) : 0.0f;
            d.x *= inv; d.y *= inv; d.z *= inv; d.w *= inv;
            n5 = n4; n4 = n3; n3 = n2; n2 = n1; n1 = n0; n0 = d;
            const int pos = tt + 1;
            float4 acc;
            if (pos >= 6) {
                acc.x = cf[0]*n0.x + cf[1]*n1.x + cf[2]*n2.x + cf[3]*n3.x + cf[4]*n4.x + cf[5]*n5.x;
                acc.y = cf[0]*n0.y + cf[1]*n1.y + cf[2]*n2.y + cf[3]*n3.y + cf[4]*n4.y + cf[5]*n5.y;
                acc.z = cf[0]*n0.z + cf[1]*n1.z + cf[2]*n2.z + cf[3]*n3.z + cf[4]*n4.z + cf[5]*n5.z;
                acc.w = cf[0]*n0.w + cf[1]*n1.w + cf[2]*n2.w + cf[3]*n3.w + cf[4]*n4.w + cf[5]*n5.w;
            } else {
                float wk[5] = {0.f, 0.f, 0.f, 0.f, 0.f};
                float wsum = 0.0f;
                if (pos == 1) {
                    wk[0] = 0.36787944117144233f;  // exp(-1), torch.linspace(-1,0,1)
                    wsum  = wk[0];
                } else {
                    const float dn = (float)(pos - 1);
#pragma unroll
                    for (int k = 0; k < 5; ++k) {
                        if (k < pos) { wk[k] = expf(-(float)k / dn); wsum += wk[k]; }
                    }
                }
                const float c = scale / (wsum + 1e-8f);
                acc.x = c * (wk[0]*n0.x + wk[1]*n1.x + wk[2]*n2.x + wk[3]*n3.x + wk[4]*n4.x);
                acc.y = c * (wk[0]*n0.y + wk[1]*n1.y + wk[2]*n2.y + wk[3]*n3.y + wk[4]*n4.y);
                acc.z = c * (wk[0]*n0.z + wk[1]*n1.z + wk[2]*n2.z + wk[3]*n3.z + wk[4]*n4.z);
                acc.w = c * (wk[0]*n0.w + wk[1]*n1.w + wk[2]*n2.w + wk[3]*n3.w + wk[4]*n4.w);
            }
            obase[(size_t)pos * DV + lane] = acc;
        }
        obase[lane] = z4;  // pos 0 -> zeros (out poisoned, must write)
    } else {
        // ---- fast path: double-steps, unroll 3 (pipeline & ring period match) ----
        // Initial pipeline: Q0..Q5 = rows p0-7 .. p0-2.
        float4 Q0 = __ldg(&base[(size_t)(p0 - 7) * DV + lane]);
        float4 Q1 = __ldg(&base[(size_t)(p0 - 6) * DV + lane]);
        float4 Q2 = __ldg(&base[(size_t)(p0 - 5) * DV + lane]);
        float4 Q3 = __ldg(&base[(size_t)(p0 - 4) * DV + lane]);
        float4 Q4 = __ldg(&base[(size_t)(p0 - 3) * DV + lane]);
        float4 Q5 = __ldg(&base[(size_t)(p0 - 2) * DV + lane]);
        float4 R0 = z4, R1 = z4, R2 = z4, R3 = z4, R4 = z4, R5 = z4;

        // Prologue: diffs p0-7..p0-2 (diff p0-7 is dead weight in R0, aged out)
        dstep(base, obase, p0 - 1, p0,     0, lane, Q0, Q1, Q2, R0, R1, R5, R4, R3, R2, cf, red, 0, wid, lid, false, false);
        dstep(base, obase, p0 + 1, p0 + 2, 0, lane, Q2, Q3, Q4, R2, R3, R1, R0, R5, R4, cf, red, 1, wid, lid, false, false);
        dstep(base, obase, p0 + 3, p0 + 4, 0, lane, Q4, Q5, Q0, R4, R5, R3, R2, R1, R0, cf, red, 2, wid, lid, false, false);

        // Main: logical step k has PA = row p0-1+2k; outputs pos p0+2k, +1.
        const int nsteps = nout >> 1;
        int i = 0;
        for (; i + 3 <= nsteps; i += 3) {
            const int r = p0 - 1 + 2 * i;
            dstep(base, obase, min(r + 6,  S - 1), min(r + 7,  S - 1), p0 + 2*i,     lane, Q0, Q1, Q2, R0, R1, R5, R4, R3, R2, cf, red, 0, wid, lid, true, true);
            dstep(base, obase, min(r + 8,  S - 1), min(r + 9,  S - 1), p0 + 2*i + 2, lane, Q2, Q3, Q4, R2, R3, R1, R0, R5, R4, cf, red, 1, wid, lid, true, true);
            dstep(base, obase, min(r + 10, S - 1), min(r + 11, S - 1), p0 + 2*i + 4, lane, Q4, Q5, Q0, R4, R5, R3, R2, R1, R0, cf, red, 2, wid, lid, true, true);
        }
        // Remainder double-steps (0..2), pattern continues at phase 0.
        if (i < nsteps) {
            const int r = p0 - 1 + 2 * i;
            dstep(base, obase, min(r + 6, S - 1), min(r + 7, S - 1), p0 + 2*i, lane, Q0, Q1, Q2, R0, R1, R5, R4, R3, R2, cf, red, 0, wid, lid, true, true);
        }
        if (i + 1 < nsteps) {
            const int r = p0 - 1 + 2 * i;
            dstep(base, obase, min(r + 8, S - 1), min(r + 9, S - 1), p0 + 2*i + 2, lane, Q2, Q3, Q4, R2, R3, R1, R0, R5, R4, cf, red, 1, wid, lid, true, true);
        }
        // Odd final output (not hit for S=8192, kept for generality).
        if (nout & 1) {
            const int ph = nsteps % 3;
            const int r  = p0 - 1 + 2 * nsteps;
            if (ph == 0)
                dstep(base, obase, min(r + 6, S - 1), min(r + 7, S - 1), p0 + 2*nsteps, lane, Q0, Q1, Q2, R0, R1, R5, R4, R3, R2, cf, red, 0, wid, lid, true, false);
            else if (ph == 1)
                dstep(base, obase, min(r + 6, S - 1), min(r + 7, S - 1), p0 + 2*nsteps, lane, Q2, Q3, Q4, R2, R3, R1, R0, R5, R4, cf, red, 1, wid, lid, true, false);
            else
                dstep(base, obase, min(r + 6, S - 1), min(r + 7, S - 1), p0 + 2*nsteps, lane, Q4, Q5, Q0, R4, R5, R3, R2, R1, R0, cf, red, 2, wid, lid, true, false);
        }
    }
}

extern "C" void kernel_launch(void* const* d_in, const int* in_sizes, int n_in,
                              void* d_out, int out_size) {
    const float* emb = (const float*)d_in[0];
    const int*   li  = (const int*)d_in[1];
    float*       out = (float*)d_out;

    const int total = in_sizes[0];
    const int S     = total / (BATCH * D);  // 8192 for the reference shapes

    dim3 grid((S + CHUNK - 1) / CHUNK, BATCH);
    traj_flow_kernel<<<grid, NTHR>>>(emb, li, out, S);
}